// round 5
// baseline (speedup 1.0000x reference)
#include <cuda_runtime.h>
#include <cuda_fp16.h>
#include <stdint.h>

#define FULLMASK 0xFFFFFFFFu

static const int MAX_N = 100000;
static const int PAD   = 128;       // max degree slots per node (Poisson(25): P(>=128) ~ 0)
static const int PADSH = 7;

// ---------------- device scratch ----------------
__device__ __half g_h1h[MAX_N * 32];       // x @ W1, fp16, plain order, row = 64B
__device__ __half g_h2h[MAX_N * 64];       // layer-2 input, fp16, plain order, row = 128B
__device__ float  g_dinv[MAX_N];
__device__ int    g_cnt[MAX_N];            // in-degree (atomic cursor during fill)
__device__ int    g_srcpad[MAX_N * PAD];   // padded CSR: src ids of edges into node
__device__ float  g_partials[64];

// ---------------- init ----------------
__global__ void k_init(int n) {
    int i = blockIdx.x * blockDim.x + threadIdx.x;
    if (i < n) g_cnt[i] = 0;
    if (i < 64) g_partials[i] = 0.0f;
}

// ---------------- single edge pass: padded CSR fill ----------------
__global__ void k_fill(const int* __restrict__ src, const int* __restrict__ dst, int E) {
    int e = blockIdx.x * blockDim.x + threadIdx.x;
    if (e < E) {
        int s = src[e];
        int d = dst[e];
        int slot = atomicAdd(&g_cnt[d], 1);
        if (slot < PAD) g_srcpad[(d << PADSH) + slot] = s;
    }
}

// ---------------- GEMM1: h1 = x @ W1 (fp32 compute, fp16 store) + dinv fusion ----------------
__global__ void k_gemm1(const float* __restrict__ x, const float* __restrict__ W1, int n) {
    __shared__ float W1s[128 * 32];
    int tid = threadIdx.x;
    for (int idx = tid; idx < 128 * 32; idx += 256) W1s[idx] = W1[idx];

    if (tid < 32) {
        int nd = blockIdx.x * 32 + tid;
        if (nd < n) g_dinv[nd] = rsqrtf(1.0f + (float)g_cnt[nd]);
    }
    __syncthreads();

    int lane = tid & 31;
    int w    = tid >> 5;
    int node0 = (blockIdx.x * 8 + w) * 4;

    float4 xr[4];
#pragma unroll
    for (int t = 0; t < 4; t++) {
        int nd = node0 + t;
        if (nd < n) xr[t] = reinterpret_cast<const float4*>(x + (size_t)nd * 128)[lane];
        else        xr[t] = make_float4(0.f, 0.f, 0.f, 0.f);
    }
    float acc[4] = {0.f, 0.f, 0.f, 0.f};

#pragma unroll
    for (int k4 = 0; k4 < 32; k4++) {
        float w0 = W1s[(4 * k4 + 0) * 32 + lane];
        float w1 = W1s[(4 * k4 + 1) * 32 + lane];
        float w2 = W1s[(4 * k4 + 2) * 32 + lane];
        float w3 = W1s[(4 * k4 + 3) * 32 + lane];
#pragma unroll
        for (int t = 0; t < 4; t++) {
            float a0 = __shfl_sync(FULLMASK, xr[t].x, k4);
            float a1 = __shfl_sync(FULLMASK, xr[t].y, k4);
            float a2 = __shfl_sync(FULLMASK, xr[t].z, k4);
            float a3 = __shfl_sync(FULLMASK, xr[t].w, k4);
            acc[t] = fmaf(a0, w0, fmaf(a1, w1, fmaf(a2, w2, fmaf(a3, w3, acc[t]))));
        }
    }
#pragma unroll
    for (int t = 0; t < 4; t++) {
        int nd = node0 + t;
        if (nd < n) g_h1h[(size_t)nd * 32 + lane] = __float2half(acc[t]);
    }
}

// helper: accumulate uint4-of-half2 row * coef into 8 fp32 accumulators
__device__ __forceinline__ void acc_row(float* acc, uint4 v, float c) {
    __half2 p0 = *reinterpret_cast<__half2*>(&v.x);
    __half2 p1 = *reinterpret_cast<__half2*>(&v.y);
    __half2 p2 = *reinterpret_cast<__half2*>(&v.z);
    __half2 p3 = *reinterpret_cast<__half2*>(&v.w);
    float2 f0 = __half22float2(p0);
    float2 f1 = __half22float2(p1);
    float2 f2 = __half22float2(p2);
    float2 f3 = __half22float2(p3);
    acc[0] = fmaf(f0.x, c, acc[0]); acc[1] = fmaf(f0.y, c, acc[1]);
    acc[2] = fmaf(f1.x, c, acc[2]); acc[3] = fmaf(f1.y, c, acc[3]);
    acc[4] = fmaf(f2.x, c, acc[4]); acc[5] = fmaf(f2.y, c, acc[5]);
    acc[6] = fmaf(f3.x, c, acc[6]); acc[7] = fmaf(f3.y, c, acc[7]);
}

// ---------------- agg layer1 + relu + GEMM2 fused ----------------
// warp per node; lane = (edge e = lane>>2, feature block f = lane&3 -> features 8f..8f+7)
// 8 edges per iteration, one LDG.128 per lane.
__global__ void k_agg1_gemm2(const float* __restrict__ b1, const float* __restrict__ W2, int n) {
    __shared__ float b1s[32];
    __shared__ float W2s[32 * 64];
    int tid = threadIdx.x;
    if (tid < 32) b1s[tid] = b1[tid];
    for (int idx = tid; idx < 32 * 64; idx += 256) W2s[idx] = W2[idx];
    __syncthreads();

    int lane = tid & 31;
    int w    = tid >> 5;
    int node = blockIdx.x * 8 + w;
    if (node >= n) return;

    int e = lane >> 2;      // 0..7
    int f = lane & 3;       // 0..3 -> features 8f..8f+7

    float di   = g_dinv[node];
    int   base = node << PADSH;
    int   cnt  = g_cnt[node]; if (cnt > PAD) cnt = PAD;

    float acc[8] = {0.f, 0.f, 0.f, 0.f, 0.f, 0.f, 0.f, 0.f};

    int j = 0;
    for (; j + 8 <= cnt; j += 8) {
        int s = g_srcpad[base + j + e];
        float c = g_dinv[s] * di;
        uint4 v = *reinterpret_cast<const uint4*>(&g_h1h[(size_t)s * 32 + f * 8]);
        acc_row(acc, v, c);
    }
    if (j < cnt) {
        bool valid = (j + e) < cnt;
        int s = valid ? g_srcpad[base + j + e] : node;
        float c = valid ? g_dinv[s] * di : 0.0f;
        uint4 v = *reinterpret_cast<const uint4*>(&g_h1h[(size_t)s * 32 + f * 8]);
        acc_row(acc, v, c);
    }

    // reduce across e (masks 4, 8, 16)
#pragma unroll
    for (int m = 4; m <= 16; m <<= 1) {
#pragma unroll
        for (int i = 0; i < 8; i++) acc[i] += __shfl_xor_sync(FULLMASK, acc[i], m);
    }

    // self-loop + bias + relu -> z[0..7] = z1[8f..8f+7]
    float dd = di * di;
    uint4 sv = *reinterpret_cast<const uint4*>(&g_h1h[(size_t)node * 32 + f * 8]);
    float z[8];
    {
        __half2 p0 = *reinterpret_cast<__half2*>(&sv.x);
        __half2 p1 = *reinterpret_cast<__half2*>(&sv.y);
        __half2 p2 = *reinterpret_cast<__half2*>(&sv.z);
        __half2 p3 = *reinterpret_cast<__half2*>(&sv.w);
        float2 f0 = __half22float2(p0);
        float2 f1 = __half22float2(p1);
        float2 f2 = __half22float2(p2);
        float2 f3 = __half22float2(p3);
        float sf[8] = {f0.x, f0.y, f1.x, f1.y, f2.x, f2.y, f3.x, f3.y};
#pragma unroll
        for (int i = 0; i < 8; i++)
            z[i] = fmaxf(acc[i] + b1s[8 * f + i] + sf[i] * dd, 0.0f);
    }

    // GEMM2: lane computes output features (2*lane, 2*lane+1)
    float o0 = 0.f, o1 = 0.f;
#pragma unroll
    for (int k = 0; k < 32; k++) {
        float zk = __shfl_sync(FULLMASK, z[k & 7], k >> 3);  // z1[k] from lane (k>>3)
        float2 wv = *reinterpret_cast<const float2*>(&W2s[k * 64 + 2 * lane]);
        o0 = fmaf(zk, wv.x, o0);
        o1 = fmaf(zk, wv.y, o1);
    }
    // plain order store: features (2*lane, 2*lane+1) at offset 2*lane
    *reinterpret_cast<__half2*>(&g_h2h[(size_t)node * 64 + 2 * lane]) = __floats2half2_rn(o0, o1);
}

// ---------------- agg layer2 + relu + MLP head + per-graph partial sums ----------------
// warp per node; lane = (edge e = lane>>3, block q = lane&7 -> features 8q..8q+7)
// 4 edges per iteration, one LDG.128 per lane.
__global__ void k_agg2_mlp(const float* __restrict__ b2, const float* __restrict__ Wm1,
                           const float* __restrict__ bm1, const float* __restrict__ Wm2,
                           const float* __restrict__ bm2, int n, int num_nodes, int nbatch) {
    __shared__ float b2s[64];
    __shared__ float Wm1s[64 * 64];
    __shared__ float bm1s[64];
    __shared__ float Wm2s[64];
    __shared__ float redv[8];
    __shared__ int   redb[8];

    int tid = threadIdx.x;
    if (tid < 64) { b2s[tid] = b2[tid]; bm1s[tid] = bm1[tid]; Wm2s[tid] = Wm2[tid]; }
    for (int idx = tid; idx < 64 * 64; idx += 256) Wm1s[idx] = Wm1[idx];
    __syncthreads();

    int lane = tid & 31;
    int w    = tid >> 5;
    int node = blockIdx.x * 8 + w;
    bool active = (node < n);

    int e = lane >> 3;      // 0..3
    int q = lane & 7;       // 0..7 -> features 8q..8q+7

    float di = 0.f; int base = 0, cnt = 0;
    if (active) {
        di = g_dinv[node];
        base = node << PADSH;
        cnt = g_cnt[node]; if (cnt > PAD) cnt = PAD;
    }

    float acc[8] = {0.f, 0.f, 0.f, 0.f, 0.f, 0.f, 0.f, 0.f};

    int j = 0;
    for (; j + 4 <= cnt; j += 4) {
        int s = g_srcpad[base + j + e];
        float c = g_dinv[s] * di;
        uint4 v = *reinterpret_cast<const uint4*>(&g_h2h[(size_t)s * 64 + q * 8]);
        acc_row(acc, v, c);
    }
    if (active && j < cnt) {
        bool valid = (j + e) < cnt;
        int s = valid ? g_srcpad[base + j + e] : node;
        float c = valid ? g_dinv[s] * di : 0.0f;
        uint4 v = *reinterpret_cast<const uint4*>(&g_h2h[(size_t)s * 64 + q * 8]);
        acc_row(acc, v, c);
    }

    // reduce across e (masks 8, 16)
#pragma unroll
    for (int m = 8; m <= 16; m <<= 1) {
#pragma unroll
        for (int i = 0; i < 8; i++) acc[i] += __shfl_xor_sync(FULLMASK, acc[i], m);
    }

    // self-loop + bias + relu -> z[0..7] = z2[8q..8q+7]
    float z[8] = {0.f, 0.f, 0.f, 0.f, 0.f, 0.f, 0.f, 0.f};
    if (active) {
        float dd = di * di;
        uint4 sv = *reinterpret_cast<const uint4*>(&g_h2h[(size_t)node * 64 + q * 8]);
        __half2 p0 = *reinterpret_cast<__half2*>(&sv.x);
        __half2 p1 = *reinterpret_cast<__half2*>(&sv.y);
        __half2 p2 = *reinterpret_cast<__half2*>(&sv.z);
        __half2 p3 = *reinterpret_cast<__half2*>(&sv.w);
        float2 f0 = __half22float2(p0);
        float2 f1 = __half22float2(p1);
        float2 f2 = __half22float2(p2);
        float2 f3 = __half22float2(p3);
        float sf[8] = {f0.x, f0.y, f1.x, f1.y, f2.x, f2.y, f3.x, f3.y};
#pragma unroll
        for (int i = 0; i < 8; i++)
            z[i] = fmaxf(acc[i] + b2s[8 * q + i] + sf[i] * dd, 0.0f);
    }

    // MLP hidden: lane owns m[2*lane], m[2*lane+1]
    float m0 = bm1s[2 * lane], m1 = bm1s[2 * lane + 1];
#pragma unroll
    for (int k = 0; k < 64; k++) {
        float zk = __shfl_sync(FULLMASK, z[k & 7], k >> 3);  // z2[k] from lane (k>>3)
        float2 wv = *reinterpret_cast<const float2*>(&Wm1s[k * 64 + 2 * lane]);
        m0 = fmaf(zk, wv.x, m0);
        m1 = fmaf(zk, wv.y, m1);
    }
    m0 = fmaxf(m0, 0.0f);
    m1 = fmaxf(m1, 0.0f);

    float p = m0 * Wm2s[2 * lane] + m1 * Wm2s[2 * lane + 1];
    p += __shfl_xor_sync(FULLMASK, p, 16);
    p += __shfl_xor_sync(FULLMASK, p, 8);
    p += __shfl_xor_sync(FULLMASK, p, 4);
    p += __shfl_xor_sync(FULLMASK, p, 2);
    p += __shfl_xor_sync(FULLMASK, p, 1);

    int batch = active ? (node / num_nodes) : -1;
    if (batch >= nbatch) batch = -1;
    if (lane == 0) {
        redv[w] = (batch >= 0) ? (p + bm2[0]) : 0.0f;
        redb[w] = batch;
    }
    __syncthreads();

    if (tid == 0) {
        int bA = -1, bB = -1; float sA = 0.f, sB = 0.f;
        for (int k = 0; k < 8; k++) {
            int b = redb[k];
            if (b < 0) continue;
            if (bA < 0 || b == bA) { bA = b; sA += redv[k]; }
            else                   { bB = b; sB += redv[k]; }
        }
        if (bA >= 0) atomicAdd(&g_partials[bA], sA);
        if (bB >= 0) atomicAdd(&g_partials[bB], sB);
    }
}

// ---------------- final: mean ----------------
__global__ void k_final(float* __restrict__ out, int nbatch, float inv_num_nodes) {
    int i = threadIdx.x;
    if (i < nbatch) out[i] = g_partials[i] * inv_num_nodes;
}

// ---------------- host launch ----------------
extern "C" void kernel_launch(void* const* d_in, const int* in_sizes, int n_in,
                              void* d_out, int out_size) {
    const float* x   = (const float*)d_in[0];
    const float* W1c = (const float*)d_in[1];
    const float* b1c = (const float*)d_in[2];
    const float* W2c = (const float*)d_in[3];
    const float* b2c = (const float*)d_in[4];
    const float* Wm1 = (const float*)d_in[5];
    const float* bm1 = (const float*)d_in[6];
    const float* Wm2 = (const float*)d_in[7];
    const float* bm2 = (const float*)d_in[8];
    const int*   ei  = (const int*)d_in[9];
    float* out = (float*)d_out;

    int N = in_sizes[0] / 128;
    int E = in_sizes[9] / 2;
    const int* src = ei;
    const int* dst = ei + E;

    int nbatch = out_size;
    int num_nodes = N / (nbatch > 0 ? nbatch : 1);

    k_init<<<(N + 255) / 256, 256>>>(N);
    k_fill<<<(E + 255) / 256, 256>>>(src, dst, E);
    k_gemm1<<<(N + 31) / 32, 256>>>(x, W1c, N);
    k_agg1_gemm2<<<(N + 7) / 8, 256>>>(b1c, W2c, N);
    k_agg2_mlp<<<(N + 7) / 8, 256>>>(b2c, Wm1, bm1, Wm2, bm2, N, num_nodes, nbatch);
    k_final<<<1, 64>>>(out, nbatch, 1.0f / (float)num_nodes);
}